// round 17
// baseline (speedup 1.0000x reference)
#include <cuda_runtime.h>
#include <cuda_fp16.h>
#include <cstdint>

#define NT 512
#define TILE 512        // 16 warps * 32 rows
#define SSTR 21         // f32 scratch stride (conflict-free: gcd(21,32)=1)

// ---- smem layout (byte offsets) ----
#define OFF_BP1 0            // 16nt*2kb*32*8B  = 8192
#define OFF_BP2 8192         // 16nt*8kb*32*8B  = 32768
#define OFF_BP3 40960        // 2nt*8kb*32*8B   = 4096
#define OFF_BS0 45056        // 128 f32
#define OFF_BS1 45568        // 128 f32
#define OFF_BS2 46080        // 16 f32
#define OFF_S   46144        // 16 warps * 32 rows * 21 f32 * 4B = 43008
#define SMEM_BYTES (OFF_S + 43008)   // 89152

__device__ __forceinline__ uint32_t pack_h2(float a, float b) {
    __half2 h = __floats2half2_rn(a, b);
    return *(uint32_t*)&h;
}

__device__ __forceinline__ void mma_f16(float& d0, float& d1, float& d2, float& d3,
                                        uint32_t a0, uint32_t a1, uint32_t a2, uint32_t a3,
                                        uint32_t b0, uint32_t b1) {
    asm("mma.sync.aligned.m16n8k16.row.col.f32.f16.f16.f32 "
        "{%0,%1,%2,%3}, {%4,%5,%6,%7}, {%8,%9}, {%0,%1,%2,%3};"
        : "+f"(d0), "+f"(d1), "+f"(d2), "+f"(d3)
        : "r"(a0), "r"(a1), "r"(a2), "r"(a3), "r"(b0), "r"(b1));
}

__device__ __forceinline__ void mat3mul(float* C, const float* A, const float* Bm) {
    #pragma unroll
    for (int i = 0; i < 3; i++)
        #pragma unroll
        for (int j = 0; j < 3; j++)
            C[i*3+j] = A[i*3]*Bm[j] + A[i*3+1]*Bm[3+j] + A[i*3+2]*Bm[6+j];
}

__global__ void __launch_bounds__(NT, 1)
l2t_reg_kernel(const float* __restrict__ y,
               const float* __restrict__ ow0, const float* __restrict__ ob0,
               const float* __restrict__ ow1, const float* __restrict__ ob1,
               const float* __restrict__ ow2, const float* __restrict__ ob2,
               const float* __restrict__ tw0, const float* __restrict__ tb0,
               const float* __restrict__ tw1, const float* __restrict__ tb1,
               const float* __restrict__ tw2, const float* __restrict__ tb2,
               float* __restrict__ out, int tiles)
{
    extern __shared__ char smc[];
    uint2* Bp1 = (uint2*)(smc + OFF_BP1);
    uint2* Bp2 = (uint2*)(smc + OFF_BP2);
    uint2* Bp3 = (uint2*)(smc + OFF_BP3);
    float* bs0 = (float*)(smc + OFF_BS0);
    float* bs1 = (float*)(smc + OFF_BS1);
    float* bs2 = (float*)(smc + OFF_BS2);

    const int tid  = threadIdx.x;
    const int wid  = tid >> 5;
    const int lane = tid & 31;
    const int qr   = lane >> 2;   // 0..7
    const int qc   = lane & 3;    // 0..3
    float* Sw = (float*)(smc + OFF_S) + wid * 32 * SSTR;

    #pragma unroll 1
    for (int ph = 0; ph < 2; ++ph) {
        const float* w0 = ph ? tw0 : ow0;  const float* b0 = ph ? tb0 : ob0;
        const float* w1 = ph ? tw1 : ow1;  const float* b1 = ph ? tb1 : ob1;
        const float* w2 = ph ? tw2 : ow2;  const float* b2 = ph ? tb2 : ob2;
        const int nout = ph ? 3 : 9;

        __syncthreads();   // previous phase fully done with packed weights

        // ---- pack weights into fp16 B-fragment order ----
        // frag lane l: n = nt*8 + (l>>2), k = kb*16 + 2*(l&3)
        for (int i = tid; i < 16*2*32; i += NT) {            // W0 [128][32], KB=2
            int l = i & 31, kb = (i >> 5) & 1, nt = i >> 6;
            int n = nt*8 + (l >> 2), k = kb*16 + 2*(l & 3);
            Bp1[i] = make_uint2(pack_h2(w0[n*32 + k],     w0[n*32 + k + 1]),
                                pack_h2(w0[n*32 + k + 8], w0[n*32 + k + 9]));
        }
        for (int i = tid; i < 16*8*32; i += NT) {            // W1 [128][128], KB=8
            int l = i & 31, kb = (i >> 5) & 7, nt = i >> 8;
            int n = nt*8 + (l >> 2), k = kb*16 + 2*(l & 3);
            Bp2[i] = make_uint2(pack_h2(w1[n*128 + k],     w1[n*128 + k + 1]),
                                pack_h2(w1[n*128 + k + 8], w1[n*128 + k + 9]));
        }
        for (int i = tid; i < 2*8*32; i += NT) {             // W2 [nout][128] pad N16
            int l = i & 31, kb = (i >> 5) & 7, nt = i >> 8;
            int n = nt*8 + (l >> 2), k = kb*16 + 2*(l & 3);
            uint2 v = make_uint2(0u, 0u);
            if (n < nout)
                v = make_uint2(pack_h2(w2[n*128 + k],     w2[n*128 + k + 1]),
                               pack_h2(w2[n*128 + k + 8], w2[n*128 + k + 9]));
            Bp3[i] = v;
        }
        if (tid < 128) { bs0[tid] = b0[tid]; bs1[tid] = b1[tid]; }
        if (tid < 16)  bs2[tid] = (tid < nout) ? b2[tid] : 0.f;
        __syncthreads();

        #pragma unroll 1
        for (int t = blockIdx.x; t < tiles; t += gridDim.x) {
            const int m0 = t * TILE + wid * 32;

            // ---- Layer 1: A from gmem (K=32 -> 2 k16-blocks) ----
            uint32_t A1[2][2][4];
            #pragma unroll
            for (int g = 0; g < 2; ++g) {
                const float* yb = y + (size_t)(m0 + g*16 + qr) * 64 + ph * 32;
                #pragma unroll
                for (int kb = 0; kb < 2; ++kb) {
                    const int base = kb*16 + 2*qc;
                    float2 v0 = __ldg((const float2*)(yb + base));
                    float2 v1 = __ldg((const float2*)(yb + 512 + base));
                    float2 v2 = __ldg((const float2*)(yb + base + 8));
                    float2 v3 = __ldg((const float2*)(yb + 512 + base + 8));
                    A1[g][kb][0] = pack_h2(v0.x, v0.y);
                    A1[g][kb][1] = pack_h2(v1.x, v1.y);
                    A1[g][kb][2] = pack_h2(v2.x, v2.y);
                    A1[g][kb][3] = pack_h2(v3.x, v3.y);
                }
            }

            // Layer 1 -> A2 fragments directly in registers
            uint32_t A2[2][8][4];
            #pragma unroll
            for (int nt = 0; nt < 16; ++nt) {
                float d[2][4] = {{0.f,0.f,0.f,0.f},{0.f,0.f,0.f,0.f}};
                #pragma unroll
                for (int kb = 0; kb < 2; ++kb) {
                    uint2 bb = Bp1[(nt*2 + kb)*32 + lane];
                    mma_f16(d[0][0], d[0][1], d[0][2], d[0][3],
                            A1[0][kb][0], A1[0][kb][1], A1[0][kb][2], A1[0][kb][3], bb.x, bb.y);
                    mma_f16(d[1][0], d[1][1], d[1][2], d[1][3],
                            A1[1][kb][0], A1[1][kb][1], A1[1][kb][2], A1[1][kb][3], bb.x, bb.y);
                }
                const int col = nt*8 + 2*qc;
                const float bv0 = bs0[col], bv1 = bs0[col+1];
                const int kb2 = nt >> 1;
                const int s01 = (nt & 1) ? 2 : 0;   // a0/a1 (even nt) or a2/a3 (odd nt)
                #pragma unroll
                for (int g = 0; g < 2; ++g) {
                    A2[g][kb2][s01]     = pack_h2(fmaxf(d[g][0] + bv0, 0.f),
                                                  fmaxf(d[g][1] + bv1, 0.f));
                    A2[g][kb2][s01 + 1] = pack_h2(fmaxf(d[g][2] + bv0, 0.f),
                                                  fmaxf(d[g][3] + bv1, 0.f));
                }
            }

            // ---- Layer 2 (nt-pairs: 4 independent chains) + fused Layer 3 ----
            float D3[2][2][4] = {};   // [nt3][g][..]
            uint32_t A3[2][4];
            const int ntmax3 = ph ? 1 : 2;
            #pragma unroll
            for (int np = 0; np < 8; ++np) {          // nt = 2*np, 2*np+1
                float d[2][2][4] = {};                 // [p][g][4]
                #pragma unroll
                for (int kb = 0; kb < 8; ++kb) {
                    uint2 bb0 = Bp2[((2*np + 0)*8 + kb)*32 + lane];
                    uint2 bb1 = Bp2[((2*np + 1)*8 + kb)*32 + lane];
                    mma_f16(d[0][0][0], d[0][0][1], d[0][0][2], d[0][0][3],
                            A2[0][kb][0], A2[0][kb][1], A2[0][kb][2], A2[0][kb][3], bb0.x, bb0.y);
                    mma_f16(d[0][1][0], d[0][1][1], d[0][1][2], d[0][1][3],
                            A2[1][kb][0], A2[1][kb][1], A2[1][kb][2], A2[1][kb][3], bb0.x, bb0.y);
                    mma_f16(d[1][0][0], d[1][0][1], d[1][0][2], d[1][0][3],
                            A2[0][kb][0], A2[0][kb][1], A2[0][kb][2], A2[0][kb][3], bb1.x, bb1.y);
                    mma_f16(d[1][1][0], d[1][1][1], d[1][1][2], d[1][1][3],
                            A2[1][kb][0], A2[1][kb][1], A2[1][kb][2], A2[1][kb][3], bb1.x, bb1.y);
                }
                #pragma unroll
                for (int p = 0; p < 2; ++p) {
                    const int nt  = 2*np + p;
                    const int col = nt*8 + 2*qc;
                    const float bv0 = bs1[col], bv1 = bs1[col+1];
                    const int s01 = p ? 2 : 0;
                    #pragma unroll
                    for (int g = 0; g < 2; ++g) {
                        A3[g][s01]     = pack_h2(fmaxf(d[p][g][0] + bv0, 0.f),
                                                 fmaxf(d[p][g][1] + bv1, 0.f));
                        A3[g][s01 + 1] = pack_h2(fmaxf(d[p][g][2] + bv0, 0.f),
                                                 fmaxf(d[p][g][3] + bv1, 0.f));
                    }
                }
                // A3 for kb2 = np complete -> consume now
                #pragma unroll
                for (int nt3 = 0; nt3 < 2; ++nt3) {
                    if (nt3 >= ntmax3) break;
                    uint2 bb = Bp3[(nt3*8 + np)*32 + lane];
                    mma_f16(D3[nt3][0][0], D3[nt3][0][1], D3[nt3][0][2], D3[nt3][0][3],
                            A3[0][0], A3[0][1], A3[0][2], A3[0][3], bb.x, bb.y);
                    mma_f16(D3[nt3][1][0], D3[nt3][1][1], D3[nt3][1][2], D3[nt3][1][3],
                            A3[1][0], A3[1][1], A3[1][2], A3[1][3], bb.x, bb.y);
                }
            }

            // ---- scatter D3 (+bias) to scratch for row-major gather ----
            #pragma unroll
            for (int nt3 = 0; nt3 < 2; ++nt3) {
                if (nt3 >= ntmax3) break;
                const int col = nt3*8 + 2*qc;
                const float bv0 = bs2[col], bv1 = bs2[col+1];
                #pragma unroll
                for (int g = 0; g < 2; ++g) {
                    Sw[(g*16 + qr)*SSTR + col]         = D3[nt3][g][0] + bv0;
                    Sw[(g*16 + qr)*SSTR + col + 1]     = D3[nt3][g][1] + bv1;
                    Sw[(g*16 + qr + 8)*SSTR + col]     = D3[nt3][g][2] + bv0;
                    Sw[(g*16 + qr + 8)*SSTR + col + 1] = D3[nt3][g][3] + bv1;
                }
            }
            __syncwarp();

            // ---- epilogue: one row per lane ----
            if (ph == 0) {
                float A[9], T[9], M[9];
                #pragma unroll
                for (int j = 0; j < 9; ++j) A[j] = Sw[lane*SSTR + j];

                float n0 = fabsf(A[0]) + fabsf(A[1]) + fabsf(A[2]);
                float n1 = fabsf(A[3]) + fabsf(A[4]) + fabsf(A[5]);
                float n2 = fabsf(A[6]) + fabsf(A[7]) + fabsf(A[8]);
                float nrm = fmaxf(n0, fmaxf(n1, n2));
                int s = 0;
                if (nrm > 0.25f) {
                    s = (int)ceilf(log2f(nrm * 4.0f));
                    if (s < 0) s = 0;
                    float sc = exp2f(-(float)s);
                    #pragma unroll
                    for (int j = 0; j < 9; ++j) A[j] *= sc;
                }
                // order-8 Taylor (scaled ||A|| <= 0.25 -> remainder ~1e-11)
                #pragma unroll
                for (int j = 0; j < 9; ++j) T[j] = A[j] * (1.0f/8.0f);
                T[0] += 1.f; T[4] += 1.f; T[8] += 1.f;
                #pragma unroll
                for (int jj = 7; jj >= 1; --jj) {
                    mat3mul(M, A, T);
                    float rc = 1.0f / (float)jj;
                    #pragma unroll
                    for (int j = 0; j < 9; ++j) T[j] = M[j] * rc;
                    T[0] += 1.f; T[4] += 1.f; T[8] += 1.f;
                }
                for (int q = 0; q < s; ++q) {
                    mat3mul(M, T, T);
                    #pragma unroll
                    for (int j = 0; j < 9; ++j) T[j] = M[j];
                }
                const size_t row = (size_t)m0 + lane;
                #pragma unroll
                for (int j = 0; j < 9; ++j) out[row*12 + j] = T[j];
            } else {
                const size_t row = (size_t)m0 + lane;
                #pragma unroll
                for (int j = 0; j < 3; ++j)
                    out[row*12 + 9 + j] = Sw[lane*SSTR + j];
            }
            __syncwarp();  // scratch reads done before next tile overwrites Sw
        }
    }
}

extern "C" void kernel_launch(void* const* d_in, const int* in_sizes, int n_in,
                              void* d_out, int out_size)
{
    const float* y   = (const float*)d_in[0];
    const float* ow0 = (const float*)d_in[1];
    const float* ob0 = (const float*)d_in[2];
    const float* ow1 = (const float*)d_in[3];
    const float* ob1 = (const float*)d_in[4];
    const float* ow2 = (const float*)d_in[5];
    const float* ob2 = (const float*)d_in[6];
    const float* tw0 = (const float*)d_in[7];
    const float* tb0 = (const float*)d_in[8];
    const float* tw1 = (const float*)d_in[9];
    const float* tb1 = (const float*)d_in[10];
    const float* tw2 = (const float*)d_in[11];
    const float* tb2 = (const float*)d_in[12];
    float* out = (float*)d_out;

    const int Bn = in_sizes[0] / 64;
    const int tiles = Bn / TILE;                 // 256 for B=131072

    int sms = 148;
    cudaDeviceGetAttribute(&sms, cudaDevAttrMultiProcessorCount, 0);
    int grid = tiles < sms ? tiles : sms;

    cudaFuncSetAttribute(l2t_reg_kernel, cudaFuncAttributeMaxDynamicSharedMemorySize, SMEM_BYTES);
    l2t_reg_kernel<<<grid, NT, SMEM_BYTES>>>(y, ow0, ob0, ow1, ob1, ow2, ob2,
                                             tw0, tb0, tw1, tb1, tw2, tb2, out, tiles);
}